// round 10
// baseline (speedup 1.0000x reference)
#include <cuda_runtime.h>
#include <cuda_bf16.h>
#include <stdint.h>
#include <math.h>
#include <string.h>

#define BN 64
#define TT 32
#define HD 1024
#define LL 196

// ---------------- device scratch --------------------------------------------
// Weights: uint4 records per (gate-col j, ks, qp): {B0hi, B0lo, B1hi, B1lo}
__device__ uint4 g_w0p[(size_t)4096 * 256];      // w_ih1  (K=1024)
__device__ uint4 g_w1p[(size_t)4096 * 256];      // w_hh1  (K=1024)
__device__ uint4 g_wip[(size_t)4096 * 512];      // w_ih2  (K=2048)
__device__ uint4 g_w2p[(size_t)4096 * 256];      // w_hh2  (K=1024)
// Activations (uint4 A-records): record (row, ks*4+qpair) = {hi01, lo01, hi89, lo89}
__device__ uint4 g_h1p[2][BN * 256], g_h2p[2][BN * 256];
__device__ uint4 g_vap[BN * 256];
__device__ float g_X1p[(size_t)2048 * 4096];     // x@w_ih1^T + biases (fp32, permuted)
__device__ float g_h1f[BN * HD];
__device__ float g_c1[BN * HD], g_c2[BN * HD];
__device__ float g_alpha[BN * LL];
__device__ float g_bs1[4096], g_bs2[4096];       // permuted bias sums

__device__ __forceinline__ float sigf(float x) { return 1.0f / (1.0f + expf(-x)); }

__device__ __forceinline__ uint32_t bfbits(__nv_bfloat16 h) {
    unsigned short s; memcpy(&s, &h, 2); return (uint32_t)s;
}

// pair index p (elements 2p,2p+1) -> uint2 slot in A-record layout
__device__ __forceinline__ int pair_slot(int p) {
    int ks = p >> 3, w = p & 7;
    return ks * 8 + ((w & 3) << 1) + (w >> 2);
}

// split a float2 into packed bf16 hi and lo words
__device__ __forceinline__ void split2(float2 v, uint32_t& hi, uint32_t& lo) {
    __nv_bfloat16 h0 = __float2bfloat16(v.x);
    __nv_bfloat16 h1 = __float2bfloat16(v.y);
    __nv_bfloat16 l0 = __float2bfloat16(v.x - __bfloat162float(h0));
    __nv_bfloat16 l1 = __float2bfloat16(v.y - __bfloat162float(h1));
    hi = bfbits(h0) | (bfbits(h1) << 16);
    lo = bfbits(l0) | (bfbits(l1) << 16);
}

__device__ __forceinline__ void mma_bf16(float c[4],
    uint32_t a0, uint32_t a1, uint32_t a2, uint32_t a3,
    uint32_t b0, uint32_t b1)
{
    asm volatile(
        "mma.sync.aligned.m16n8k16.row.col.f32.bf16.bf16.f32 "
        "{%0,%1,%2,%3}, {%4,%5,%6,%7}, {%8,%9}, {%0,%1,%2,%3};"
        : "+f"(c[0]), "+f"(c[1]), "+f"(c[2]), "+f"(c[3])
        : "r"(a0), "r"(a1), "r"(a2), "r"(a3), "r"(b0), "r"(b1));
}

// ---------------- single fused setup kernel ---------------------------------
// block ranges: [0,8192) w0p | [8192,16384) w1p | [16384,32768) wip |
//               [32768,40960) w2p | [40960,41088) zero | [41088,41104) bias
__device__ __forceinline__ void conv_one(const float* __restrict__ w,
                                         uint2* __restrict__ dst,
                                         int Kw, int lg, int idx) {
    int j  = idx >> lg;
    int kp = idx & ((1 << lg) - 1);
    int src = (j & 3) * 1024 + (j >> 2);               // gate-interleave perm
    float v0 = w[(size_t)src * Kw + 2 * kp];
    float v1 = w[(size_t)src * Kw + 2 * kp + 1];
    uint32_t hi, lo;
    split2(make_float2(v0, v1), hi, lo);
    int ks = kp >> 3, qp = kp & 3, half = (kp >> 2) & 1;
    dst[((size_t)j << lg) + ks * 8 + qp * 2 + half] = make_uint2(hi, lo);
}

__global__ __launch_bounds__(256) void setup_all(
    const float* __restrict__ w_ih1, const float* __restrict__ w_hh1,
    const float* __restrict__ w_ih2, const float* __restrict__ w_hh2,
    const float* __restrict__ b_ih1, const float* __restrict__ b_hh1,
    const float* __restrict__ b_ih2, const float* __restrict__ b_hh2)
{
    int b = blockIdx.x;
    int tid = threadIdx.x;
    if (b < 8192) {
        conv_one(w_ih1, (uint2*)g_w0p, 1024, 9, b * 256 + tid);
    } else if (b < 16384) {
        conv_one(w_hh1, (uint2*)g_w1p, 1024, 9, (b - 8192) * 256 + tid);
    } else if (b < 32768) {
        conv_one(w_ih2, (uint2*)g_wip, 2048, 10, (b - 16384) * 256 + tid);
    } else if (b < 40960) {
        conv_one(w_hh2, (uint2*)g_w2p, 1024, 9, (b - 32768) * 256 + tid);
    } else if (b < 41088) {
        int i = (b - 40960) * 256 + tid;                  // 0 .. 32767
        if (i < BN * 256) {
            uint4 z = make_uint4(0u, 0u, 0u, 0u);
            g_h1p[0][i] = z; g_h1p[1][i] = z;
            g_h2p[0][i] = z; g_h2p[1][i] = z;
        }
        if (i < BN * HD / 2) {
            g_c1[2 * i] = 0.f; g_c1[2 * i + 1] = 0.f;
            g_c2[2 * i] = 0.f; g_c2[2 * i + 1] = 0.f;
        }
    } else {
        int j = (b - 41088) * 256 + tid;
        if (j < 4096) {
            int src = (j & 3) * 1024 + (j >> 2);
            g_bs1[j] = b_ih1[src] + b_hh1[src];
            g_bs2[j] = b_ih2[src] + b_hh2[src];
        }
    }
}

// ---------------- X1 GEMM (tensor): X1p = emb[tok] @ w_ih1'^T + bs1 ---------
// gather + hi/lo split fused into the A path (reads emb directly).
// grid (128 col-slabs, 32 row-tiles), block 128 (4 warps, each m16 x n32)
__global__ __launch_bounds__(128) void mma_x1(const int* __restrict__ inp,
                                              const float* __restrict__ emb) {
    const int lane = threadIdx.x & 31;
    const int warp = threadIdx.x >> 5;
    const int slab = blockIdx.x * 32;
    const int rbase = blockIdx.y * 64;
    const int r_lo = warp * 16 + (lane >> 2);
    const int qpair = lane & 3;
    const int qk = qpair * 2;
    const int qp = lane & 3;

    float c[4][4] = {};

    const int tok0 = inp[rbase + r_lo];
    const int tok1 = inp[rbase + r_lo + 8];
    const float* E0 = emb + (size_t)tok0 * 1024;
    const float* E1 = emb + (size_t)tok1 * 1024;

    for (int ks = 0; ks < 64; ks++) {
        int e0 = ks * 16 + qk;
        float2 a0 = *(const float2*)(E0 + e0);
        float2 b0 = *(const float2*)(E0 + e0 + 8);
        float2 a1 = *(const float2*)(E1 + e0);
        float2 b1 = *(const float2*)(E1 + e0 + 8);
        uint32_t h01_0, l01_0, h89_0, l89_0, h01_1, l01_1, h89_1, l89_1;
        split2(a0, h01_0, l01_0);  split2(b0, h89_0, l89_0);
        split2(a1, h01_1, l01_1);  split2(b1, h89_1, l89_1);
        #pragma unroll
        for (int tl = 0; tl < 4; tl++) {
            int j = slab + tl * 8 + (lane >> 2);
            uint4 B = g_w0p[(size_t)j * 256 + ks * 4 + qp];
            mma_bf16(c[tl], h01_0, h01_1, h89_0, h89_1, B.x, B.z);
            mma_bf16(c[tl], h01_0, h01_1, h89_0, h89_1, B.y, B.w);
            mma_bf16(c[tl], l01_0, l01_1, l89_0, l89_1, B.x, B.z);
        }
    }

    #pragma unroll
    for (int tl = 0; tl < 4; tl++) {
        int j0 = slab + tl * 8 + qk;
        float2 bs = *(const float2*)(g_bs1 + j0);
        int row0 = rbase + r_lo;
        *(float2*)(g_X1p + (size_t)row0 * 4096 + j0) =
            make_float2(c[tl][0] + bs.x, c[tl][1] + bs.y);
        *(float2*)(g_X1p + (size_t)(row0 + 8) * 4096 + j0) =
            make_float2(c[tl][2] + bs.x, c[tl][3] + bs.y);
    }
}

// ---------------- fused tensor-core LSTM cell, split-K x8 -------------------
// grid 128 (col slabs of 32 gate-interleaved cols = 8 d's), block 1024 (32 warps):
// warp = kslice(0..7) * 4 + wr(0..3).  wr -> m16 rows; kslice -> K/8 slice.
__global__ __launch_bounds__(1024) void mma_cell(
    int mode, int t,
    const uint4* __restrict__ a0p,
    const uint4* __restrict__ a1p,
    const uint4* __restrict__ a2p,
    uint4* __restrict__ hout,
    float* __restrict__ c_state, float* __restrict__ fout)
{
    extern __shared__ float red[];          // [8][4][32][17]
    #define RED(ksl, wr, ln, a) red[(((ksl) * 4 + (wr)) * 32 + (ln)) * 17 + (a)]

    const int lane   = threadIdx.x & 31;
    const int warp   = threadIdx.x >> 5;
    const int kslice = warp >> 2;
    const int wr     = warp & 3;
    const int slab   = blockIdx.x * 32;
    const int r_lo   = wr * 16 + (lane >> 2);
    const int qpair  = lane & 3;
    const int qk = qpair * 2;
    const int qp = lane & 3;

    float c[4][4] = {};

    const int nseg = (mode == 1) ? 1 : 3;
    const uint4* AP[3] = {a0p, a1p, a2p};
    const uint4* WP[3];
    int PITCH4[3], KOFF4[3];
    if (mode == 1) {
        WP[0] = g_w1p; PITCH4[0] = 256; KOFF4[0] = 0;
    } else {
        WP[0] = g_wip; PITCH4[0] = 512; KOFF4[0] = 0;
        WP[1] = g_wip; PITCH4[1] = 512; KOFF4[1] = 256;
        WP[2] = g_w2p; PITCH4[2] = 256; KOFF4[2] = 0;
    }

    for (int s = 0; s < nseg; s++) {
        const uint4* A0 = AP[s] + (size_t)r_lo * 256;
        const uint4* A1 = AP[s] + (size_t)(r_lo + 8) * 256;
        const uint4* W = WP[s];
        const int pit = PITCH4[s];
        const int ko  = KOFF4[s];
        #pragma unroll 4
        for (int it = 0; it < 8; it++) {
            const int ks = kslice * 8 + it;       // this warp's K slice
            uint4 q0 = A0[ks * 4 + qpair];
            uint4 q1 = A1[ks * 4 + qpair];
            #pragma unroll
            for (int tl = 0; tl < 4; tl++) {
                int j = slab + tl * 8 + (lane >> 2);
                uint4 B = W[(size_t)j * pit + ko + ks * 4 + qp];
                mma_bf16(c[tl], q0.x, q1.x, q0.z, q1.z, B.x, B.z);
                mma_bf16(c[tl], q0.x, q1.x, q0.z, q1.z, B.y, B.w);
                mma_bf16(c[tl], q0.y, q1.y, q0.w, q1.w, B.x, B.z);
            }
        }
    }

    // write partials to smem
    #pragma unroll
    for (int tl = 0; tl < 4; tl++)
        #pragma unroll
        for (int i = 0; i < 4; i++)
            RED(kslice, wr, lane, tl * 4 + i) = c[tl][i];
    __syncthreads();

    if (warp >= 4) return;   // epilogue on warps 0-3 (kslice==0, wr==warp)

    // reduce 8 k-slices
    #pragma unroll
    for (int tl = 0; tl < 4; tl++)
        #pragma unroll
        for (int i = 0; i < 4; i++) {
            float v = 0.f;
            #pragma unroll
            for (int ksl = 0; ksl < 8; ksl++)
                v += RED(ksl, wr, lane, tl * 4 + i);
            c[tl][i] = v;
        }

    // epilogue: addend, lane-pair gate exchange, activation, pair-packed h write
    const bool has_if = ((lane & 1) == 0);   // even lanes hold gates {i,f}
    const int d = (slab >> 2);               // d base for this slab (8 d's)
    const int pbase = blockIdx.x * 4;        // pair base (d/2)

    #pragma unroll
    for (int tl = 0; tl < 4; tl++) {
        int j0 = slab + tl * 8 + qk;
        float x0, x1, x2, x3;
        if (mode == 1) {
            const float* x1p = g_X1p + (size_t)(t * 64 + r_lo) * 4096 + j0;
            float2 aL = *(const float2*)x1p;
            float2 aH = *(const float2*)(x1p + 8 * 4096);
            x0 = c[tl][0] + aL.x; x1 = c[tl][1] + aL.y;
            x2 = c[tl][2] + aH.x; x3 = c[tl][3] + aH.y;
        } else {
            float2 bs = *(const float2*)(g_bs2 + j0);
            x0 = c[tl][0] + bs.x; x1 = c[tl][1] + bs.y;
            x2 = c[tl][2] + bs.x; x3 = c[tl][3] + bs.y;
        }
        float y0 = __shfl_xor_sync(0xffffffffu, x0, 1);
        float y1 = __shfl_xor_sync(0xffffffffu, x1, 1);
        float y2 = __shfl_xor_sync(0xffffffffu, x2, 1);
        float y3 = __shfl_xor_sync(0xffffffffu, x3, 1);

        if (has_if) {
            int dd = d + tl * 2 + ((lane & 3) >> 1);   // lane&3==0 -> +0, ==2 -> +1
            int pair = pbase + tl;
            #pragma unroll
            for (int rr = 0; rr < 2; rr++) {
                float iv = rr ? x2 : x0;
                float fv = rr ? x3 : x1;
                float gv = rr ? y2 : y0;
                float ov = rr ? y3 : y1;
                int n = r_lo + rr * 8;
                int idx = n * 1024 + dd;
                float ig = sigf(iv), fg = sigf(fv);
                float gg = tanhf(gv), og = sigf(ov);
                float cn = fg * c_state[idx] + ig * gg;
                c_state[idx] = cn;
                float hn = og * tanhf(cn);
                __nv_bfloat16 hh = __float2bfloat16(hn);
                uint32_t hib = bfbits(hh);
                uint32_t lob = bfbits(__float2bfloat16(hn - __bfloat162float(hh)));
                uint32_t myv = hib | (lob << 16);
                uint32_t ov2 = __shfl_xor_sync(0x55555555u, myv, 2);
                if ((lane & 3) == 0) {
                    uint2 w;
                    w.x = (myv & 0xffffu) | ((ov2 & 0xffffu) << 16);   // hi pair
                    w.y = (myv >> 16) | (ov2 & 0xffff0000u);           // lo pair
                    ((uint2*)hout)[(size_t)n * 512 + pair_slot(pair)] = w;
                }
                if (mode == 1) fout[idx] = hn;                      // h1f for attention
                else fout[(size_t)(t * 64 + n) * 1024 + dd] = hn;   // output
            }
        }
    }
    #undef RED
}

// ---------------- attention (fp32 SIMT, high parallelism) -------------------
__global__ __launch_bounds__(256) void attn_alpha(const float* __restrict__ img) {
    __shared__ float sh[1024];
    const int n = blockIdx.x;
    const int lbase = blockIdx.y * 28;
    {
        int i = threadIdx.x;
        *(float4*)&sh[i * 4] = *(const float4*)(g_h1f + (size_t)n * 1024 + i * 4);
    }
    __syncthreads();

    const int w = threadIdx.x >> 5;
    const int lane = threadIdx.x & 31;
    for (int l = lbase + w; l < lbase + 28; l += 8) {
        const float* f = img + ((size_t)n * LL + l) * 1024;
        float s = 0.f;
        #pragma unroll
        for (int i = 0; i < 8; i++) {
            int dd = i * 128 + lane * 4;
            float4 fv = *(const float4*)(f + dd);
            s += fv.x * sh[dd] + fv.y * sh[dd + 1] + fv.z * sh[dd + 2] + fv.w * sh[dd + 3];
        }
        #pragma unroll
        for (int off = 16; off; off >>= 1)
            s += __shfl_xor_sync(0xffffffffu, s, off);
        if (lane == 0) g_alpha[n * LL + l] = s;
    }
}

__global__ __launch_bounds__(256) void attn_vatt(const float* __restrict__ img) {
    __shared__ float sa[LL];
    const int n = blockIdx.x;
    const int tid = threadIdx.x;
    const int d = blockIdx.y * 256 + tid;
    if (tid < LL) sa[tid] = g_alpha[n * LL + tid];
    __syncthreads();

    const float* f = img + (size_t)n * LL * 1024 + d;
    float s = 0.f;
    #pragma unroll 4
    for (int l = 0; l < LL; l++)
        s += sa[l] * f[(size_t)l * 1024];

    __nv_bfloat16 h = __float2bfloat16(s);
    uint32_t hib = bfbits(h);
    uint32_t lob = bfbits(__float2bfloat16(s - __bfloat162float(h)));
    uint32_t myv = hib | (lob << 16);
    uint32_t ov = __shfl_xor_sync(0xffffffffu, myv, 1);
    if ((tid & 1) == 0) {
        uint2 w;
        w.x = (myv & 0xffffu) | ((ov & 0xffffu) << 16);
        w.y = (myv >> 16) | (ov & 0xffff0000u);
        ((uint2*)g_vap)[(size_t)n * 512 + pair_slot(d >> 1)] = w;
    }
}

// ---------------- launch -----------------------------------------------------
extern "C" void kernel_launch(void* const* d_in, const int* in_sizes, int n_in,
                              void* d_out, int out_size)
{
    const int*   inputs = (const int*)  d_in[0];
    const float* img    = (const float*)d_in[1];
    const float* emb    = (const float*)d_in[2];
    const float* w_ih1  = (const float*)d_in[3];
    const float* w_hh1  = (const float*)d_in[4];
    const float* b_ih1  = (const float*)d_in[5];
    const float* b_hh1  = (const float*)d_in[6];
    const float* w_ih2  = (const float*)d_in[7];
    const float* w_hh2  = (const float*)d_in[8];
    const float* b_ih2  = (const float*)d_in[9];
    const float* b_hh2  = (const float*)d_in[10];
    float* out = (float*)d_out;
    (void)in_sizes; (void)n_in; (void)out_size;

    const int RED_BYTES = 8 * 4 * 32 * 17 * 4;   // 69632

    static uint4 *h1p[2], *h2p[2], *vap;
    static float *c1p, *c2p, *h1fp;
    static bool init = false;
    if (!init) {
        void* tmp;
        cudaGetSymbolAddress(&tmp, g_h1p); h1p[0] = (uint4*)tmp; h1p[1] = h1p[0] + BN * 256;
        cudaGetSymbolAddress(&tmp, g_h2p); h2p[0] = (uint4*)tmp; h2p[1] = h2p[0] + BN * 256;
        cudaGetSymbolAddress(&tmp, g_vap); vap = (uint4*)tmp;
        cudaGetSymbolAddress(&tmp, g_c1);  c1p = (float*)tmp;
        cudaGetSymbolAddress(&tmp, g_c2);  c2p = (float*)tmp;
        cudaGetSymbolAddress(&tmp, g_h1f); h1fp = (float*)tmp;
        cudaFuncSetAttribute(mma_cell, cudaFuncAttributeMaxDynamicSharedMemorySize,
                             RED_BYTES);
        init = true;
    }

    // launch #0: all setup (weight conv + zero + bias) in one kernel
    setup_all<<<41104, 256>>>(w_ih1, w_hh1, w_ih2, w_hh2,
                              b_ih1, b_hh1, b_ih2, b_hh2);
    // launch #1: X1 precompute with fused gather+split
    mma_x1<<<dim3(128, 32), 128>>>(inputs, emb);

    // loop: launches #2.. ; ncu -s 5 -c 1 captures launch #5 = first cell2
    for (int t = 0; t < TT; t++) {
        const int p = t & 1;
        mma_cell<<<128, 1024, RED_BYTES>>>(1, t,
            h1p[p], nullptr, nullptr,
            h1p[1 - p], c1p, h1fp);
        attn_alpha<<<dim3(64, 7), 256>>>(img);
        attn_vatt<<<dim3(64, 4), 256>>>(img);
        mma_cell<<<128, 1024, RED_BYTES>>>(2, t,
            vap, h1p[1 - p], h2p[p],
            h2p[1 - p], c2p, out);
    }
}

// round 11
// speedup vs baseline: 1.0932x; 1.0932x over previous
#include <cuda_runtime.h>
#include <cuda_bf16.h>
#include <stdint.h>
#include <math.h>
#include <string.h>

#define BN 64
#define TT 32
#define HD 1024
#define LL 196
#define LT 28            // attention tile rows

// ---------------- device scratch --------------------------------------------
__device__ uint4 g_w0p[(size_t)4096 * 256];      // w_ih1  (K=1024)
__device__ uint4 g_w1p[(size_t)4096 * 256];      // w_hh1  (K=1024)
__device__ uint4 g_wip[(size_t)4096 * 512];      // w_ih2  (K=2048)
__device__ uint4 g_w2p[(size_t)4096 * 256];      // w_hh2  (K=1024)
__device__ uint4 g_xp[(size_t)2048 * 256];       // embedded inputs (A-records)
__device__ uint4 g_h1p[2][BN * 256], g_h2p[2][BN * 256];
__device__ uint4 g_vap[BN * 256];
__device__ float g_X1p[(size_t)2048 * 4096];     // x@w_ih1^T + biases (fp32, permuted)
__device__ float g_h1f[BN * HD];
__device__ float g_c1[BN * HD], g_c2[BN * HD];
__device__ float g_bs1[4096], g_bs2[4096];       // permuted bias sums

__device__ __forceinline__ float sigf(float x) { return 1.0f / (1.0f + expf(-x)); }

__device__ __forceinline__ uint32_t bfbits(__nv_bfloat16 h) {
    unsigned short s; memcpy(&s, &h, 2); return (uint32_t)s;
}

__device__ __forceinline__ int pair_slot(int p) {
    int ks = p >> 3, w = p & 7;
    return ks * 8 + ((w & 3) << 1) + (w >> 2);
}

__device__ __forceinline__ void split2(float2 v, uint32_t& hi, uint32_t& lo) {
    __nv_bfloat16 h0 = __float2bfloat16(v.x);
    __nv_bfloat16 h1 = __float2bfloat16(v.y);
    __nv_bfloat16 l0 = __float2bfloat16(v.x - __bfloat162float(h0));
    __nv_bfloat16 l1 = __float2bfloat16(v.y - __bfloat162float(h1));
    hi = bfbits(h0) | (bfbits(h1) << 16);
    lo = bfbits(l0) | (bfbits(l1) << 16);
}

__device__ __forceinline__ void mma_bf16(float c[4],
    uint32_t a0, uint32_t a1, uint32_t a2, uint32_t a3,
    uint32_t b0, uint32_t b1)
{
    asm volatile(
        "mma.sync.aligned.m16n8k16.row.col.f32.bf16.bf16.f32 "
        "{%0,%1,%2,%3}, {%4,%5,%6,%7}, {%8,%9}, {%0,%1,%2,%3};"
        : "+f"(c[0]), "+f"(c[1]), "+f"(c[2]), "+f"(c[3])
        : "r"(a0), "r"(a1), "r"(a2), "r"(a3), "r"(b0), "r"(b1));
}

// ---------------- setup kernels (R9-proven) ----------------------------------
__global__ void zero_state() {
    int i = blockIdx.x * blockDim.x + threadIdx.x;
    if (i < BN * 256) {
        uint4 z = make_uint4(0u, 0u, 0u, 0u);
        g_h1p[0][i] = z; g_h1p[1][i] = z;
        g_h2p[0][i] = z; g_h2p[1][i] = z;
    }
    if (i < BN * HD / 2) {
        g_c1[2 * i] = 0.f; g_c1[2 * i + 1] = 0.f;
        g_c2[2 * i] = 0.f; g_c2[2 * i + 1] = 0.f;
    }
}

__global__ __launch_bounds__(256) void conv_w(const float* __restrict__ w,
                                              uint2* __restrict__ dst,
                                              int Kw, int lg) {
    int idx = blockIdx.x * blockDim.x + threadIdx.x;
    if (idx >= (4096 << lg)) return;
    int j  = idx >> lg;
    int kp = idx & ((1 << lg) - 1);
    int src = (j & 3) * 1024 + (j >> 2);
    float v0 = w[(size_t)src * Kw + 2 * kp];
    float v1 = w[(size_t)src * Kw + 2 * kp + 1];
    uint32_t hi, lo;
    split2(make_float2(v0, v1), hi, lo);
    int ks = kp >> 3, qp = kp & 3, half = (kp >> 2) & 1;
    dst[((size_t)j << lg) + ks * 8 + qp * 2 + half] = make_uint2(hi, lo);
}

__global__ void bias_prep(const float* b_ih1, const float* b_hh1,
                          const float* b_ih2, const float* b_hh2) {
    int j = blockIdx.x * blockDim.x + threadIdx.x;
    if (j < 4096) {
        int src = (j & 3) * 1024 + (j >> 2);
        g_bs1[j] = b_ih1[src] + b_hh1[src];
        g_bs2[j] = b_ih2[src] + b_hh2[src];
    }
}

__global__ __launch_bounds__(256) void gather_conv(const int* __restrict__ inp,
                                                   const float* __restrict__ emb) {
    int idx = blockIdx.x * blockDim.x + threadIdx.x;   // pair idx
    int row = idx >> 9;
    int p   = idx & 511;
    int tok = inp[row];
    float v0 = emb[(size_t)tok * 1024 + 2 * p];
    float v1 = emb[(size_t)tok * 1024 + 2 * p + 1];
    uint32_t hi, lo;
    split2(make_float2(v0, v1), hi, lo);
    ((uint2*)g_xp)[(size_t)row * 512 + pair_slot(p)] = make_uint2(hi, lo);
}

// ---------------- X1 GEMM (tensor) ------------------------------------------
__global__ __launch_bounds__(128) void mma_x1() {
    const int lane = threadIdx.x & 31;
    const int warp = threadIdx.x >> 5;
    const int slab = blockIdx.x * 32;
    const int rbase = blockIdx.y * 64;
    const int r_lo = warp * 16 + (lane >> 2);
    const int qpair = lane & 3;
    const int qk = qpair * 2;
    const int qp = lane & 3;

    float c[4][4] = {};

    const uint4* A0 = g_xp + (size_t)(rbase + r_lo) * 256;
    const uint4* A1 = g_xp + (size_t)(rbase + r_lo + 8) * 256;

    for (int ks = 0; ks < 64; ks++) {
        uint4 q0 = A0[ks * 4 + qpair];
        uint4 q1 = A1[ks * 4 + qpair];
        #pragma unroll
        for (int tl = 0; tl < 4; tl++) {
            int j = slab + tl * 8 + (lane >> 2);
            uint4 B = g_w0p[(size_t)j * 256 + ks * 4 + qp];
            mma_bf16(c[tl], q0.x, q1.x, q0.z, q1.z, B.x, B.z);
            mma_bf16(c[tl], q0.x, q1.x, q0.z, q1.z, B.y, B.w);
            mma_bf16(c[tl], q0.y, q1.y, q0.w, q1.w, B.x, B.z);
        }
    }

    #pragma unroll
    for (int tl = 0; tl < 4; tl++) {
        int j0 = slab + tl * 8 + qk;
        float2 bs = *(const float2*)(g_bs1 + j0);
        int row0 = rbase + r_lo;
        *(float2*)(g_X1p + (size_t)row0 * 4096 + j0) =
            make_float2(c[tl][0] + bs.x, c[tl][1] + bs.y);
        *(float2*)(g_X1p + (size_t)(row0 + 8) * 4096 + j0) =
            make_float2(c[tl][2] + bs.x, c[tl][3] + bs.y);
    }
}

// ---------------- fused tensor-core LSTM cell, split-K x8 (R9) --------------
__global__ __launch_bounds__(1024) void mma_cell(
    int mode, int t,
    const uint4* __restrict__ a0p,
    const uint4* __restrict__ a1p,
    const uint4* __restrict__ a2p,
    uint4* __restrict__ hout,
    float* __restrict__ c_state, float* __restrict__ fout)
{
    extern __shared__ float red[];          // [8][4][32][17]
    #define RED(ksl, wr, ln, a) red[(((ksl) * 4 + (wr)) * 32 + (ln)) * 17 + (a)]

    const int lane   = threadIdx.x & 31;
    const int warp   = threadIdx.x >> 5;
    const int kslice = warp >> 2;
    const int wr     = warp & 3;
    const int slab   = blockIdx.x * 32;
    const int r_lo   = wr * 16 + (lane >> 2);
    const int qpair  = lane & 3;
    const int qk = qpair * 2;
    const int qp = lane & 3;

    float c[4][4] = {};

    const int nseg = (mode == 1) ? 1 : 3;
    const uint4* AP[3] = {a0p, a1p, a2p};
    const uint4* WP[3];
    int PITCH4[3], KOFF4[3];
    if (mode == 1) {
        WP[0] = g_w1p; PITCH4[0] = 256; KOFF4[0] = 0;
    } else {
        WP[0] = g_wip; PITCH4[0] = 512; KOFF4[0] = 0;
        WP[1] = g_wip; PITCH4[1] = 512; KOFF4[1] = 256;
        WP[2] = g_w2p; PITCH4[2] = 256; KOFF4[2] = 0;
    }

    for (int s = 0; s < nseg; s++) {
        const uint4* A0 = AP[s] + (size_t)r_lo * 256;
        const uint4* A1 = AP[s] + (size_t)(r_lo + 8) * 256;
        const uint4* W = WP[s];
        const int pit = PITCH4[s];
        const int ko  = KOFF4[s];
        #pragma unroll 4
        for (int it = 0; it < 8; it++) {
            const int ks = kslice * 8 + it;
            uint4 q0 = A0[ks * 4 + qpair];
            uint4 q1 = A1[ks * 4 + qpair];
            #pragma unroll
            for (int tl = 0; tl < 4; tl++) {
                int j = slab + tl * 8 + (lane >> 2);
                uint4 B = W[(size_t)j * pit + ko + ks * 4 + qp];
                mma_bf16(c[tl], q0.x, q1.x, q0.z, q1.z, B.x, B.z);
                mma_bf16(c[tl], q0.x, q1.x, q0.z, q1.z, B.y, B.w);
                mma_bf16(c[tl], q0.y, q1.y, q0.w, q1.w, B.x, B.z);
            }
        }
    }

    #pragma unroll
    for (int tl = 0; tl < 4; tl++)
        #pragma unroll
        for (int i = 0; i < 4; i++)
            RED(kslice, wr, lane, tl * 4 + i) = c[tl][i];
    __syncthreads();

    if (warp >= 4) return;

    #pragma unroll
    for (int tl = 0; tl < 4; tl++)
        #pragma unroll
        for (int i = 0; i < 4; i++) {
            float v = 0.f;
            #pragma unroll
            for (int ksl = 0; ksl < 8; ksl++)
                v += RED(ksl, wr, lane, tl * 4 + i);
            c[tl][i] = v;
        }

    const bool has_if = ((lane & 1) == 0);
    const int d = (slab >> 2);
    const int pbase = blockIdx.x * 4;

    #pragma unroll
    for (int tl = 0; tl < 4; tl++) {
        int j0 = slab + tl * 8 + qk;
        float x0, x1, x2, x3;
        if (mode == 1) {
            const float* x1p = g_X1p + (size_t)(t * 64 + r_lo) * 4096 + j0;
            float2 aL = *(const float2*)x1p;
            float2 aH = *(const float2*)(x1p + 8 * 4096);
            x0 = c[tl][0] + aL.x; x1 = c[tl][1] + aL.y;
            x2 = c[tl][2] + aH.x; x3 = c[tl][3] + aH.y;
        } else {
            float2 bs = *(const float2*)(g_bs2 + j0);
            x0 = c[tl][0] + bs.x; x1 = c[tl][1] + bs.y;
            x2 = c[tl][2] + bs.x; x3 = c[tl][3] + bs.y;
        }
        float y0 = __shfl_xor_sync(0xffffffffu, x0, 1);
        float y1 = __shfl_xor_sync(0xffffffffu, x1, 1);
        float y2 = __shfl_xor_sync(0xffffffffu, x2, 1);
        float y3 = __shfl_xor_sync(0xffffffffu, x3, 1);

        if (has_if) {
            int dd = d + tl * 2 + ((lane & 3) >> 1);
            int pair = pbase + tl;
            #pragma unroll
            for (int rr = 0; rr < 2; rr++) {
                float iv = rr ? x2 : x0;
                float fv = rr ? x3 : x1;
                float gv = rr ? y2 : y0;
                float ov = rr ? y3 : y1;
                int n = r_lo + rr * 8;
                int idx = n * 1024 + dd;
                float ig = sigf(iv), fg = sigf(fv);
                float gg = tanhf(gv), og = sigf(ov);
                float cn = fg * c_state[idx] + ig * gg;
                c_state[idx] = cn;
                float hn = og * tanhf(cn);
                __nv_bfloat16 hh = __float2bfloat16(hn);
                uint32_t hib = bfbits(hh);
                uint32_t lob = bfbits(__float2bfloat16(hn - __bfloat162float(hh)));
                uint32_t myv = hib | (lob << 16);
                uint32_t ov2 = __shfl_xor_sync(0x55555555u, myv, 2);
                if ((lane & 3) == 0) {
                    uint2 w;
                    w.x = (myv & 0xffffu) | ((ov2 & 0xffffu) << 16);
                    w.y = (myv >> 16) | (ov2 & 0xffff0000u);
                    ((uint2*)hout)[(size_t)n * 512 + pair_slot(pair)] = w;
                }
                if (mode == 1) fout[idx] = hn;
                else fout[(size_t)(t * 64 + n) * 1024 + dd] = hn;
            }
        }
    }
    #undef RED
}

// ---------------- fused attention: img read ONCE per step -------------------
// No softmax => each l contributes independently:
//   v_att[d] = sum_l (h1 . F_l) * F_l[d]
// block per n (64 blocks, 512 threads). smem: F tile [LT][1024] + h1 + alpha.
// Phase A (per tile): warp per row computes alpha_l (same summation order as
// the old attn_alpha). Phase B: each thread accumulates 2 d's over the tile
// (same l-order as old attn_vatt) -> numerics bitwise-preserved.
// Next tile's global loads are register-prefetched during the phases.
__global__ __launch_bounds__(512) void attn_fused(const float* __restrict__ img) {
    extern __shared__ float smem[];
    float* Fs  = smem;                 // LT * 1024
    float* h1s = smem + LT * 1024;     // 1024
    float* alf = h1s + 1024;           // LT

    const int n    = blockIdx.x;
    const int tid  = threadIdx.x;
    const int w    = tid >> 5;
    const int lane = tid & 31;

    h1s[tid]       = g_h1f[(size_t)n * 1024 + tid];
    h1s[tid + 512] = g_h1f[(size_t)n * 1024 + tid + 512];

    const float4* base = (const float4*)(img + (size_t)n * LL * 1024);

    // stage tile 0 (LT*1024/4 = 7168 float4; 14 per thread)
    float4 stage[14];
    #pragma unroll
    for (int u = 0; u < 14; u++)
        stage[u] = base[tid + 512 * u];

    float2 vacc = make_float2(0.f, 0.f);
    __syncthreads();    // h1s ready

    for (int tb = 0; tb < LL; tb += LT) {
        // smem is free: store staged tile
        #pragma unroll
        for (int u = 0; u < 14; u++)
            ((float4*)Fs)[tid + 512 * u] = stage[u];
        __syncthreads();

        // prefetch next tile into regs (overlaps phases A/B)
        if (tb + LT < LL) {
            const float4* nb = base + (size_t)(tb + LT) * 256;
            #pragma unroll
            for (int u = 0; u < 14; u++)
                stage[u] = nb[tid + 512 * u];
        }

        // phase A: alpha for this tile (warp per row)
        for (int l = w; l < LT; l += 16) {
            const float* f = Fs + l * 1024;
            float s = 0.f;
            #pragma unroll
            for (int i = 0; i < 8; i++) {
                int dd = i * 128 + lane * 4;
                float4 fv = *(const float4*)(f + dd);
                s += fv.x * h1s[dd] + fv.y * h1s[dd + 1]
                   + fv.z * h1s[dd + 2] + fv.w * h1s[dd + 3];
            }
            #pragma unroll
            for (int off = 16; off; off >>= 1)
                s += __shfl_xor_sync(0xffffffffu, s, off);
            if (lane == 0) alf[l] = s;
        }
        __syncthreads();

        // phase B: accumulate v_att for d = 2*tid, 2*tid+1
        #pragma unroll
        for (int l = 0; l < LT; l++) {
            float a = alf[l];
            float2 fv = *(const float2*)(Fs + l * 1024 + 2 * tid);
            vacc.x += a * fv.x;
            vacc.y += a * fv.y;
        }
        __syncthreads();   // release smem for next tile
    }

    // pack (hi,lo) pair p = tid covering d = 2*tid, 2*tid+1
    uint32_t hi, lo;
    split2(vacc, hi, lo);
    ((uint2*)g_vap)[(size_t)n * 512 + pair_slot(tid)] = make_uint2(hi, lo);
}

// ---------------- launch -----------------------------------------------------
extern "C" void kernel_launch(void* const* d_in, const int* in_sizes, int n_in,
                              void* d_out, int out_size)
{
    const int*   inputs = (const int*)  d_in[0];
    const float* img    = (const float*)d_in[1];
    const float* emb    = (const float*)d_in[2];
    const float* w_ih1  = (const float*)d_in[3];
    const float* w_hh1  = (const float*)d_in[4];
    const float* b_ih1  = (const float*)d_in[5];
    const float* b_hh1  = (const float*)d_in[6];
    const float* w_ih2  = (const float*)d_in[7];
    const float* w_hh2  = (const float*)d_in[8];
    const float* b_ih2  = (const float*)d_in[9];
    const float* b_hh2  = (const float*)d_in[10];
    float* out = (float*)d_out;
    (void)in_sizes; (void)n_in; (void)out_size;

    const int RED_BYTES  = 8 * 4 * 32 * 17 * 4;            // 69632
    const int ATTN_BYTES = (LT * 1024 + 1024 + LT) * 4;    // 118896

    static uint4 *h1p[2], *h2p[2], *vap;
    static float *c1p, *c2p, *h1fp;
    static uint2 *w0p, *w1p, *wip, *w2p;
    static bool init = false;
    if (!init) {
        void* tmp;
        cudaGetSymbolAddress(&tmp, g_h1p); h1p[0] = (uint4*)tmp; h1p[1] = h1p[0] + BN * 256;
        cudaGetSymbolAddress(&tmp, g_h2p); h2p[0] = (uint4*)tmp; h2p[1] = h2p[0] + BN * 256;
        cudaGetSymbolAddress(&tmp, g_vap); vap = (uint4*)tmp;
        cudaGetSymbolAddress(&tmp, g_c1);  c1p = (float*)tmp;
        cudaGetSymbolAddress(&tmp, g_c2);  c2p = (float*)tmp;
        cudaGetSymbolAddress(&tmp, g_h1f); h1fp = (float*)tmp;
        cudaGetSymbolAddress(&tmp, g_w0p); w0p = (uint2*)tmp;
        cudaGetSymbolAddress(&tmp, g_w1p); w1p = (uint2*)tmp;
        cudaGetSymbolAddress(&tmp, g_wip); wip = (uint2*)tmp;
        cudaGetSymbolAddress(&tmp, g_w2p); w2p = (uint2*)tmp;
        cudaFuncSetAttribute(mma_cell, cudaFuncAttributeMaxDynamicSharedMemorySize,
                             RED_BYTES);
        cudaFuncSetAttribute(attn_fused, cudaFuncAttributeMaxDynamicSharedMemorySize,
                             ATTN_BYTES);
        init = true;
    }

    zero_state<<<128, 256>>>();
    conv_w<<<(4096 * 512 + 255) / 256, 256>>>(w_ih1, w0p, 1024, 9);
    conv_w<<<(4096 * 512 + 255) / 256, 256>>>(w_hh1, w1p, 1024, 9);
    conv_w<<<(4096 * 1024 + 255) / 256, 256>>>(w_ih2, wip, 2048, 10);
    conv_w<<<(4096 * 512 + 255) / 256, 256>>>(w_hh2, w2p, 1024, 9);
    bias_prep<<<16, 256>>>(b_ih1, b_hh1, b_ih2, b_hh2);
    gather_conv<<<(2048 * 512) / 256, 256>>>(inputs, emb);
    mma_x1<<<dim3(128, 32), 128>>>();

    for (int t = 0; t < TT; t++) {
        const int p = t & 1;
        mma_cell<<<128, 1024, RED_BYTES>>>(1, t,
            h1p[p], nullptr, nullptr,
            h1p[1 - p], c1p, h1fp);
        attn_fused<<<64, 512, ATTN_BYTES>>>(img);
        mma_cell<<<128, 1024, RED_BYTES>>>(2, t,
            vap, h1p[1 - p], h2p[p],
            h2p[1 - p], c2p, out);
    }
}